// round 2
// baseline (speedup 1.0000x reference)
#include <cuda_runtime.h>
#include <cstdint>

#define N_NODES  50000
#define N_EDGES  800000
#define HID      128
#define EDGE_D   16
#define N_GRAPHS 64

#define ETILE 128
#define NTILE 32
#define NUM_ETILES (N_EDGES / ETILE)

typedef unsigned long long ull;

// ---------------- device scratch (static, no allocation) ----------------
__device__ float g_hAB[(size_t)N_NODES * 256];   // hA | hB  (51.2 MB)
__device__ float g_agg[(size_t)N_NODES * HID];   // scatter target (25.6 MB)
__device__ float g_Wcat[128 * 256];              // [We1a | We1b] rearranged
__device__ float g_pool[N_GRAPHS * HID];
__device__ float g_cnt[N_GRAPHS];
__device__ int   g_row[N_EDGES];
__device__ int   g_col[N_EDGES];
__device__ int   g_batch[N_NODES];
__device__ int   g_is64;

__device__ __forceinline__ float silu_f(float v) {
    return __fdividef(v, 1.0f + __expf(-v));
}

// ---------------- packed fp32x2 helpers (sm_103a FFMA2) ----------------
__device__ __forceinline__ ull dup2(float a) {
    ull r;
    asm("mov.b64 %0, {%1, %1};" : "=l"(r) : "f"(a));
    return r;
}
__device__ __forceinline__ void ffma2(ull& acc, ull a, ull b) {
    asm("fma.rn.f32x2 %0, %1, %2, %0;" : "+l"(acc) : "l"(a), "l"(b));
}
__device__ __forceinline__ ull add2(ull a, ull b) {
    ull r;
    asm("add.rn.f32x2 %0, %1, %2;" : "=l"(r) : "l"(a), "l"(b));
    return r;
}
__device__ __forceinline__ float2 unpack2(ull v) {
    float2 r;
    asm("mov.b64 {%0, %1}, %2;" : "=f"(r.x), "=f"(r.y) : "l"(v));
    return r;
}

// ---------------- small prep kernels ----------------
__global__ void k_detect(const void* __restrict__ ei) {
    const unsigned int* p = (const unsigned int*)ei;
    int is64 = 1;
    for (int i = 0; i < 16; i++) if (p[2 * i + 1] != 0u) is64 = 0;
    g_is64 = is64;
}

__global__ void k_cvt_idx(const void* __restrict__ ei, const void* __restrict__ batch) {
    const int i = blockIdx.x * blockDim.x + threadIdx.x;
    const bool is64 = (g_is64 != 0);
    if (i < N_EDGES) {
        if (is64) {
            const long long* p = (const long long*)ei;
            g_row[i] = (int)p[i];
            g_col[i] = (int)p[N_EDGES + i];
        } else {
            const int* p = (const int*)ei;
            g_row[i] = p[i];
            g_col[i] = p[N_EDGES + i];
        }
    }
    if (i < N_NODES) {
        if (is64) g_batch[i] = (int)((const long long*)batch)[i];
        else      g_batch[i] = ((const int*)batch)[i];
    }
}

__global__ void k_zero_agg() {
    const int i = blockIdx.x * blockDim.x + threadIdx.x;
    if (i < (N_NODES * HID) / 4)
        reinterpret_cast<float4*>(g_agg)[i] = make_float4(0.f, 0.f, 0.f, 0.f);
}

__global__ void k_zero_pool() {
    const int i = blockIdx.x * blockDim.x + threadIdx.x;
    if (i < N_GRAPHS * HID) g_pool[i] = 0.f;
    if (i < N_GRAPHS)       g_cnt[i] = 0.f;
}

__global__ void k_prep_wcat(const float* __restrict__ We1) {
    const int i = blockIdx.x * blockDim.x + threadIdx.x;
    if (i < 128 * 256) {
        const int k = i >> 8, c = i & 255;
        g_Wcat[i] = (c < 128) ? We1[k * 128 + c] : We1[(128 + k) * 128 + (c - 128)];
    }
}

// ---------------- node pre-GEMM: g_hAB[n] = h[n] @ [We1a|We1b] (+be1 on cols<128)
__global__ __launch_bounds__(256) void k_node_pre(const float* __restrict__ h,
                                                  const float* __restrict__ be1) {
    __shared__ float a_s[128 * 36];           // h tile, k-major [k][n], pad 36
    const int n0 = blockIdx.x * NTILE;
    const int t = threadIdx.x;
    {
        const int n  = t >> 3;
        const int k4 = t & 7;
        const int ng = n0 + n;
#pragma unroll
        for (int j = 0; j < 4; j++) {
            const int k = k4 * 16 + j * 4;
            float4 v = make_float4(0.f, 0.f, 0.f, 0.f);
            if (ng < N_NODES) v = *reinterpret_cast<const float4*>(h + (size_t)ng * 128 + k);
            a_s[(k + 0) * 36 + n] = v.x;
            a_s[(k + 1) * 36 + n] = v.y;
            a_s[(k + 2) * 36 + n] = v.z;
            a_s[(k + 3) * 36 + n] = v.w;
        }
    }
    __syncthreads();
    const int cg = t & 31;                    // 32 groups x 8 cols = 256
    const int ng = t >> 5;                    // 8 groups x 4 nodes
    ull acc[4][4];                            // 4 nodes x 4 col-pairs
#pragma unroll
    for (int i = 0; i < 4; i++)
#pragma unroll
        for (int j = 0; j < 4; j++) acc[i][j] = 0ULL;

    const float* wbase = g_Wcat + cg * 8;
    for (int k = 0; k < 128; k++) {
        const float4 a = *reinterpret_cast<const float4*>(&a_s[k * 36 + ng * 4]);
        const ulonglong2 w01 = *reinterpret_cast<const ulonglong2*>(wbase + k * 256);
        const ulonglong2 w23 = *reinterpret_cast<const ulonglong2*>(wbase + k * 256 + 4);
        const ull ad[4] = {dup2(a.x), dup2(a.y), dup2(a.z), dup2(a.w)};
#pragma unroll
        for (int i = 0; i < 4; i++) {
            ffma2(acc[i][0], ad[i], w01.x);
            ffma2(acc[i][1], ad[i], w01.y);
            ffma2(acc[i][2], ad[i], w23.x);
            ffma2(acc[i][3], ad[i], w23.y);
        }
    }
    const int cbase = cg * 8;
    float bias[8];
#pragma unroll
    for (int j = 0; j < 8; j++) bias[j] = (cbase + j < 128) ? __ldg(be1 + cbase + j) : 0.f;
#pragma unroll
    for (int i = 0; i < 4; i++) {
        const int n = n0 + ng * 4 + i;
        if (n < N_NODES) {
            float2 p0 = unpack2(acc[i][0]), p1 = unpack2(acc[i][1]);
            float2 p2 = unpack2(acc[i][2]), p3 = unpack2(acc[i][3]);
            float4 o0 = make_float4(p0.x + bias[0], p0.y + bias[1], p1.x + bias[2], p1.y + bias[3]);
            float4 o1 = make_float4(p2.x + bias[4], p2.y + bias[5], p3.x + bias[6], p3.y + bias[7]);
            *reinterpret_cast<float4*>(g_hAB + (size_t)n * 256 + cbase)     = o0;
            *reinterpret_cast<float4*>(g_hAB + (size_t)n * 256 + cbase + 4) = o1;
        }
    }
}

// ---------------- fused edge kernel (persistent): gather + K=17 GEMM + SiLU
// ---------------- + GEMM2 (f32x2) + SiLU + vectorized scatter
#define EDGE_SMEM_FLOATS (16384 + 2048 + 128 + 128 + 16896 + 128 + 128 + 128 + 2048)
#define EDGE_SMEM_BYTES  (EDGE_SMEM_FLOATS * 4)

__global__ __launch_bounds__(512, 1) void k_edge(const float* __restrict__ x,
                                                 const float* __restrict__ ea,
                                                 const float* __restrict__ We1,
                                                 const float* __restrict__ We2,
                                                 const float* __restrict__ be2) {
    extern __shared__ float sm[];
    float* W2_s  = sm;                                    // 16384
    float* W1e_s = W2_s + 16384;                          // 2048 (16x128)
    float* W1r_s = W1e_s + 2048;                          // 128
    float* be2_s = W1r_s + 128;                           // 128
    float* u_s   = be2_s + 128;                           // 128 x 132 = 16896
    float* rad_s = u_s + 16896;                           // 128
    int*   row_s = reinterpret_cast<int*>(rad_s + 128);   // 128
    int*   col_s = row_s + 128;                           // 128
    float* ea_s  = reinterpret_cast<float*>(col_s + 128); // 2048

    const int t = threadIdx.x;

    // stage loop-invariant weights once (persistent blocks)
    for (int i = t; i < 16384; i += 512) W2_s[i] = We2[i];
    for (int i = t; i < 2048; i += 512) W1e_s[i] = We1[257 * 128 + i];
    if (t < 128) {
        W1r_s[t] = We1[256 * 128 + t];
        be2_s[t] = be2[t];
    }

    for (int tile = blockIdx.x; tile < NUM_ETILES; tile += gridDim.x) {
        const int e0 = tile * ETILE;
        __syncthreads();   // protects row_s/col_s/ea_s/u_s against prev iter readers

        for (int i = t; i < 2048; i += 512) ea_s[i] = ea[(size_t)e0 * 16 + i];
        if (t < 128) {
            const int e = e0 + t;
            const int r = g_row[e];
            const int c = g_col[e];
            row_s[t] = r;
            col_s[t] = c;
            const float dx = x[r * 3 + 0] - x[c * 3 + 0];
            const float dy = x[r * 3 + 1] - x[c * 3 + 1];
            const float dz = x[r * 3 + 2] - x[c * 3 + 2];
            rad_s[t] = dx * dx + dy * dy + dz * dz;
        }
        __syncthreads();

        // ---- Phase A: t1 = hA[row] + hB[col] + radial*W1r + ea@W1e ; u = silu(t1)
        {
            const int warp  = t >> 5;
            const int lane  = t & 31;
            const int ebase = warp * 8;
            const int co    = lane * 4;
            const ulonglong2 wr = *reinterpret_cast<const ulonglong2*>(W1r_s + co);
#pragma unroll
            for (int ii = 0; ii < 8; ii++) {
                const int e = ebase + ii;
                const ulonglong2 a2 =
                    *reinterpret_cast<const ulonglong2*>(g_hAB + (size_t)row_s[e] * 256 + co);
                const ulonglong2 b2 =
                    *reinterpret_cast<const ulonglong2*>(g_hAB + (size_t)col_s[e] * 256 + 128 + co);
                ull acc0 = add2(a2.x, b2.x);
                ull acc1 = add2(a2.y, b2.y);
                const ull radd = dup2(rad_s[e]);
                ffma2(acc0, radd, wr.x);
                ffma2(acc1, radd, wr.y);
#pragma unroll
                for (int j = 0; j < 16; j++) {
                    const ull ej = dup2(ea_s[e * 16 + j]);
                    const ulonglong2 w =
                        *reinterpret_cast<const ulonglong2*>(W1e_s + j * 128 + co);
                    ffma2(acc0, ej, w.x);
                    ffma2(acc1, ej, w.y);
                }
                const float2 f0 = unpack2(acc0);
                const float2 f1 = unpack2(acc1);
                *reinterpret_cast<float4*>(u_s + e * 132 + co) =
                    make_float4(silu_f(f0.x), silu_f(f0.y), silu_f(f1.x), silu_f(f1.y));
            }
        }
        __syncthreads();

        // ---- Phase B: v = silu(u @ W2 + be2); vectorized scatter to g_agg[row]
        {
            const int cg = t & 15;   // 16 groups x 8 cols
            const int eg = t >> 4;   // 32 groups x 4 edges
            ull acc[4][4];           // 4 edges x 4 col-pairs
#pragma unroll
            for (int i = 0; i < 4; i++)
#pragma unroll
                for (int j = 0; j < 4; j++) acc[i][j] = 0ULL;

            const float* wb = W2_s + cg * 8;
            const float* ub = u_s + (size_t)eg * 4 * 132;
#pragma unroll 4
            for (int k = 0; k < 128; k++) {
                const ulonglong2 w01 = *reinterpret_cast<const ulonglong2*>(wb + k * 128);
                const ulonglong2 w23 = *reinterpret_cast<const ulonglong2*>(wb + k * 128 + 4);
                const ull ad[4] = {dup2(ub[k]), dup2(ub[132 + k]),
                                   dup2(ub[264 + k]), dup2(ub[396 + k])};
#pragma unroll
                for (int i = 0; i < 4; i++) {
                    ffma2(acc[i][0], ad[i], w01.x);
                    ffma2(acc[i][1], ad[i], w01.y);
                    ffma2(acc[i][2], ad[i], w23.x);
                    ffma2(acc[i][3], ad[i], w23.y);
                }
            }
            const int cbase = cg * 8;
#pragma unroll
            for (int i = 0; i < 4; i++) {
                const int e = eg * 4 + i;
                float* dst = g_agg + (size_t)row_s[e] * 128 + cbase;
                const float2 p0 = unpack2(acc[i][0]);
                const float2 p1 = unpack2(acc[i][1]);
                const float2 p2 = unpack2(acc[i][2]);
                const float2 p3 = unpack2(acc[i][3]);
                const float v0 = silu_f(p0.x + be2_s[cbase + 0]);
                const float v1 = silu_f(p0.y + be2_s[cbase + 1]);
                const float v2 = silu_f(p1.x + be2_s[cbase + 2]);
                const float v3 = silu_f(p1.y + be2_s[cbase + 3]);
                const float v4 = silu_f(p2.x + be2_s[cbase + 4]);
                const float v5 = silu_f(p2.y + be2_s[cbase + 5]);
                const float v6 = silu_f(p3.x + be2_s[cbase + 6]);
                const float v7 = silu_f(p3.y + be2_s[cbase + 7]);
                asm volatile("red.global.add.v4.f32 [%0], {%1, %2, %3, %4};"
                             :: "l"(dst), "f"(v0), "f"(v1), "f"(v2), "f"(v3) : "memory");
                asm volatile("red.global.add.v4.f32 [%0], {%1, %2, %3, %4};"
                             :: "l"(dst + 4), "f"(v4), "f"(v5), "f"(v6), "f"(v7) : "memory");
            }
        }
    }
}

// ---------------- node MLP + residual + pooled scatter ----------------
#define NODE_SMEM_FLOATS (256 * 36 + 128 * 33 + 32)
#define NODE_SMEM_BYTES  (NODE_SMEM_FLOATS * 4)

__global__ __launch_bounds__(256) void k_node(const float* __restrict__ h,
                                              const float* __restrict__ Wn1,
                                              const float* __restrict__ bn1,
                                              const float* __restrict__ Wn2,
                                              const float* __restrict__ bn2) {
    extern __shared__ float sm[];
    float* a_s = sm;                      // 256 x 36 (k-major [h|agg])
    float* m_s = sm + 256 * 36;           // 128 x 33 (mid, k-major)
    int*   b_s = reinterpret_cast<int*>(sm + 256 * 36 + 128 * 33);

    const int n0 = blockIdx.x * NTILE;
    const int t = threadIdx.x;
    {
        const int n  = t >> 3;
        const int k4 = t & 7;
        const int ng = n0 + n;
#pragma unroll
        for (int j = 0; j < 4; j++) {
            const int k = k4 * 16 + j * 4;
            float4 v = make_float4(0.f, 0.f, 0.f, 0.f);
            float4 w = make_float4(0.f, 0.f, 0.f, 0.f);
            if (ng < N_NODES) {
                v = *reinterpret_cast<const float4*>(h + (size_t)ng * 128 + k);
                w = *reinterpret_cast<const float4*>(g_agg + (size_t)ng * 128 + k);
            }
            a_s[(k + 0) * 36 + n] = v.x;
            a_s[(k + 1) * 36 + n] = v.y;
            a_s[(k + 2) * 36 + n] = v.z;
            a_s[(k + 3) * 36 + n] = v.w;
            a_s[(128 + k + 0) * 36 + n] = w.x;
            a_s[(128 + k + 1) * 36 + n] = w.y;
            a_s[(128 + k + 2) * 36 + n] = w.z;
            a_s[(128 + k + 3) * 36 + n] = w.w;
        }
        if (t < 32) b_s[t] = (n0 + t < N_NODES) ? g_batch[n0 + t] : 0;
    }
    __syncthreads();

    const int cg = t & 31;  // 32 groups x 4 cols
    const int ng = t >> 5;  // 8 groups x 4 nodes
    ull acc[4][2];          // 4 nodes x 2 col-pairs
#pragma unroll
    for (int i = 0; i < 4; i++) { acc[i][0] = 0ULL; acc[i][1] = 0ULL; }

    for (int k = 0; k < 256; k++) {
        const ulonglong2 w = *reinterpret_cast<const ulonglong2*>(Wn1 + k * 128 + cg * 4);
        const float* ap = &a_s[k * 36 + ng * 4];
        const ull ad[4] = {dup2(ap[0]), dup2(ap[1]), dup2(ap[2]), dup2(ap[3])};
#pragma unroll
        for (int i = 0; i < 4; i++) {
            ffma2(acc[i][0], ad[i], w.x);
            ffma2(acc[i][1], ad[i], w.y);
        }
    }
    {
        const float b0 = __ldg(bn1 + cg * 4 + 0);
        const float b1 = __ldg(bn1 + cg * 4 + 1);
        const float b2 = __ldg(bn1 + cg * 4 + 2);
        const float b3 = __ldg(bn1 + cg * 4 + 3);
#pragma unroll
        for (int i = 0; i < 4; i++) {
            const float2 p0 = unpack2(acc[i][0]);
            const float2 p1 = unpack2(acc[i][1]);
            m_s[(cg * 4 + 0) * 33 + ng * 4 + i] = silu_f(p0.x + b0);
            m_s[(cg * 4 + 1) * 33 + ng * 4 + i] = silu_f(p0.y + b1);
            m_s[(cg * 4 + 2) * 33 + ng * 4 + i] = silu_f(p1.x + b2);
            m_s[(cg * 4 + 3) * 33 + ng * 4 + i] = silu_f(p1.y + b3);
        }
    }
    __syncthreads();

    ull acc2[4][2];
#pragma unroll
    for (int i = 0; i < 4; i++) { acc2[i][0] = 0ULL; acc2[i][1] = 0ULL; }

    for (int k = 0; k < 128; k++) {
        const ulonglong2 w = *reinterpret_cast<const ulonglong2*>(Wn2 + k * 128 + cg * 4);
        const float* ap = &m_s[k * 33 + ng * 4];
        const ull ad[4] = {dup2(ap[0]), dup2(ap[1]), dup2(ap[2]), dup2(ap[3])};
#pragma unroll
        for (int i = 0; i < 4; i++) {
            ffma2(acc2[i][0], ad[i], w.x);
            ffma2(acc2[i][1], ad[i], w.y);
        }
    }
#pragma unroll
    for (int i = 0; i < 4; i++) {
        const int n = n0 + ng * 4 + i;
        if (n < N_NODES) {
            const int b = b_s[ng * 4 + i];
            const float2 p0 = unpack2(acc2[i][0]);
            const float2 p1 = unpack2(acc2[i][1]);
            const float vals[4] = {p0.x, p0.y, p1.x, p1.y};
#pragma unroll
            for (int j = 0; j < 4; j++) {
                const int c = cg * 4 + j;
                const float hn = vals[j] + __ldg(bn2 + c) + a_s[c * 36 + ng * 4 + i];
                atomicAdd(&g_pool[b * 128 + c], hn);
            }
        }
    }
    if (t < 32 && n0 + t < N_NODES) atomicAdd(&g_cnt[b_s[t]], 1.0f);
}

__global__ void k_pool_final(float* __restrict__ out) {
    const int g = blockIdx.x;
    const int c = threadIdx.x;
    const float cnt = fmaxf(g_cnt[g], 1.0f);
    out[g * 128 + c] = g_pool[g * 128 + c] / cnt;
}

// ---------------- launcher ----------------
extern "C" void kernel_launch(void* const* d_in, const int* in_sizes, int n_in,
                              void* d_out, int out_size) {
    const float* h   = (const float*)d_in[0];
    const void*  ei  = d_in[1];
    const float* x   = (const float*)d_in[2];
    const float* ea  = (const float*)d_in[3];
    const void*  bat = d_in[4];
    const float* We1 = (const float*)d_in[5];
    const float* be1 = (const float*)d_in[6];
    const float* We2 = (const float*)d_in[7];
    const float* be2 = (const float*)d_in[8];
    const float* Wn1 = (const float*)d_in[9];
    const float* bn1 = (const float*)d_in[10];
    const float* Wn2 = (const float*)d_in[11];
    const float* bn2 = (const float*)d_in[12];
    float* out = (float*)d_out;

    cudaFuncSetAttribute(k_edge, cudaFuncAttributeMaxDynamicSharedMemorySize, EDGE_SMEM_BYTES);
    cudaFuncSetAttribute(k_node, cudaFuncAttributeMaxDynamicSharedMemorySize, NODE_SMEM_BYTES);

    k_detect<<<1, 1>>>(ei);
    k_cvt_idx<<<(N_EDGES + 255) / 256, 256>>>(ei, bat);
    k_zero_agg<<<(N_NODES * HID / 4 + 255) / 256, 256>>>();
    k_zero_pool<<<(N_GRAPHS * HID + 255) / 256, 256>>>();
    k_prep_wcat<<<(128 * 256 + 255) / 256, 256>>>(We1);
    k_node_pre<<<(N_NODES + NTILE - 1) / NTILE, 256>>>(h, be1);
    k_edge<<<152, 512, EDGE_SMEM_BYTES>>>(x, ea, We1, We2, be2);
    k_node<<<(N_NODES + NTILE - 1) / NTILE, 256, NODE_SMEM_BYTES>>>(h, Wn1, bn1, Wn2, bn2);
    k_pool_final<<<N_GRAPHS, HID>>>(out);
}

// round 3
// speedup vs baseline: 1.7610x; 1.7610x over previous
#include <cuda_runtime.h>
#include <cstdint>

#define N_NODES  50000
#define N_EDGES  800000
#define HID      128
#define EDGE_D   16
#define N_GRAPHS 64

#define ETILE 128
#define NTILE 32
#define NUM_ETILES (N_EDGES / ETILE)

// ---------------- device scratch (static, no allocation) ----------------
__device__ float g_hAB[(size_t)N_NODES * 256];   // hA | hB  (51.2 MB)
__device__ float g_agg[(size_t)N_NODES * HID];   // scatter target (25.6 MB)
__device__ float g_Wcat[128 * 256];              // [We1a | We1b] rearranged
__device__ float g_pool[N_GRAPHS * HID];
__device__ float g_cnt[N_GRAPHS];
__device__ int   g_row[N_EDGES];
__device__ int   g_col[N_EDGES];
__device__ int   g_batch[N_NODES];
__device__ int   g_is64;

__device__ __forceinline__ float silu_f(float v) {
    return __fdividef(v, 1.0f + __expf(-v));
}

// ---------------- small prep kernels ----------------
__global__ void k_detect(const void* __restrict__ ei) {
    const unsigned int* p = (const unsigned int*)ei;
    int is64 = 1;
    for (int i = 0; i < 16; i++) if (p[2 * i + 1] != 0u) is64 = 0;
    g_is64 = is64;
}

__global__ void k_cvt_idx(const void* __restrict__ ei, const void* __restrict__ batch) {
    const int i = blockIdx.x * blockDim.x + threadIdx.x;
    const bool is64 = (g_is64 != 0);
    if (i < N_EDGES) {
        if (is64) {
            const long long* p = (const long long*)ei;
            g_row[i] = (int)p[i];
            g_col[i] = (int)p[N_EDGES + i];
        } else {
            const int* p = (const int*)ei;
            g_row[i] = p[i];
            g_col[i] = p[N_EDGES + i];
        }
    }
    if (i < N_NODES) {
        if (is64) g_batch[i] = (int)((const long long*)batch)[i];
        else      g_batch[i] = ((const int*)batch)[i];
    }
}

__global__ void k_zero_agg() {
    const int i = blockIdx.x * blockDim.x + threadIdx.x;
    if (i < (N_NODES * HID) / 4)
        reinterpret_cast<float4*>(g_agg)[i] = make_float4(0.f, 0.f, 0.f, 0.f);
}

__global__ void k_zero_pool() {
    const int i = blockIdx.x * blockDim.x + threadIdx.x;
    if (i < N_GRAPHS * HID) g_pool[i] = 0.f;
    if (i < N_GRAPHS)       g_cnt[i] = 0.f;
}

__global__ void k_prep_wcat(const float* __restrict__ We1) {
    const int i = blockIdx.x * blockDim.x + threadIdx.x;
    if (i < 128 * 256) {
        const int k = i >> 8, c = i & 255;
        g_Wcat[i] = (c < 128) ? We1[k * 128 + c] : We1[(128 + k) * 128 + (c - 128)];
    }
}

// ---------------- node pre-GEMM: g_hAB[n] = h[n] @ [We1a|We1b] (+be1 on cols<128)
__global__ __launch_bounds__(256) void k_node_pre(const float* __restrict__ h,
                                                  const float* __restrict__ be1) {
    __shared__ float a_s[128 * 36];           // h tile, k-major [k][n], pad 36
    const int n0 = blockIdx.x * NTILE;
    const int t = threadIdx.x;
    {
        const int n  = t >> 3;
        const int k4 = t & 7;
        const int ng = n0 + n;
#pragma unroll
        for (int j = 0; j < 4; j++) {
            const int k = k4 * 16 + j * 4;
            float4 v = make_float4(0.f, 0.f, 0.f, 0.f);
            if (ng < N_NODES) v = *reinterpret_cast<const float4*>(h + (size_t)ng * 128 + k);
            a_s[(k + 0) * 36 + n] = v.x;
            a_s[(k + 1) * 36 + n] = v.y;
            a_s[(k + 2) * 36 + n] = v.z;
            a_s[(k + 3) * 36 + n] = v.w;
        }
    }
    __syncthreads();
    const int cg = t & 31;                    // 32 groups x 8 cols = 256
    const int ng = t >> 5;                    // 8 groups x 4 nodes
    float acc[4][8];
#pragma unroll
    for (int i = 0; i < 4; i++)
#pragma unroll
        for (int j = 0; j < 8; j++) acc[i][j] = 0.f;

    const float* wbase = g_Wcat + cg * 8;
    for (int k = 0; k < 128; k++) {
        const float4 a  = *reinterpret_cast<const float4*>(&a_s[k * 36 + ng * 4]);
        const float4 w0 = __ldg(reinterpret_cast<const float4*>(wbase + k * 256));
        const float4 w1 = __ldg(reinterpret_cast<const float4*>(wbase + k * 256 + 4));
        const float av[4] = {a.x, a.y, a.z, a.w};
        const float wv[8] = {w0.x, w0.y, w0.z, w0.w, w1.x, w1.y, w1.z, w1.w};
#pragma unroll
        for (int i = 0; i < 4; i++)
#pragma unroll
            for (int j = 0; j < 8; j++) acc[i][j] = fmaf(av[i], wv[j], acc[i][j]);
    }
    const int cbase = cg * 8;
    float bias[8];
#pragma unroll
    for (int j = 0; j < 8; j++) bias[j] = (cbase + j < 128) ? __ldg(be1 + cbase + j) : 0.f;
#pragma unroll
    for (int i = 0; i < 4; i++) {
        const int n = n0 + ng * 4 + i;
        if (n < N_NODES) {
            float4 o0 = make_float4(acc[i][0] + bias[0], acc[i][1] + bias[1],
                                    acc[i][2] + bias[2], acc[i][3] + bias[3]);
            float4 o1 = make_float4(acc[i][4] + bias[4], acc[i][5] + bias[5],
                                    acc[i][6] + bias[6], acc[i][7] + bias[7]);
            *reinterpret_cast<float4*>(g_hAB + (size_t)n * 256 + cbase)     = o0;
            *reinterpret_cast<float4*>(g_hAB + (size_t)n * 256 + cbase + 4) = o1;
        }
    }
}

// ---------------- fused edge kernel (persistent) ----------------
// Phase A: gather + K=17 GEMM + SiLU.  Phase B: GEMM2 (conflict-free LDS) + SiLU + red.v4 scatter.
#define EDGE_SMEM_FLOATS (16384 + 2048 + 128 + 128 + 16896 + 128 + 128 + 128 + 2048)
#define EDGE_SMEM_BYTES  (EDGE_SMEM_FLOATS * 4)

__global__ __launch_bounds__(512, 1) void k_edge(const float* __restrict__ x,
                                                 const float* __restrict__ ea,
                                                 const float* __restrict__ We1,
                                                 const float* __restrict__ We2,
                                                 const float* __restrict__ be2) {
    extern __shared__ float sm[];
    float* W2_s  = sm;                                    // 16384 [k][c] row-major
    float* W1e_s = W2_s + 16384;                          // 2048 (16x128)
    float* W1r_s = W1e_s + 2048;                          // 128
    float* be2_s = W1r_s + 128;                           // 128
    float* u_s   = be2_s + 128;                           // 128 x 132 = 16896
    float* rad_s = u_s + 16896;                           // 128
    int*   row_s = reinterpret_cast<int*>(rad_s + 128);   // 128
    int*   col_s = row_s + 128;                           // 128
    float* ea_s  = reinterpret_cast<float*>(col_s + 128); // 2048

    const int t = threadIdx.x;

    // stage loop-invariant weights once (persistent blocks)
    for (int i = t; i < 16384; i += 512) W2_s[i] = We2[i];
    for (int i = t; i < 2048; i += 512) W1e_s[i] = We1[257 * 128 + i];
    if (t < 128) {
        W1r_s[t] = We1[256 * 128 + t];
        be2_s[t] = be2[t];
    }

    for (int tile = blockIdx.x; tile < NUM_ETILES; tile += gridDim.x) {
        const int e0 = tile * ETILE;
        __syncthreads();   // protects smem tile buffers against prev-iter readers

        for (int i = t; i < 2048; i += 512) ea_s[i] = ea[(size_t)e0 * 16 + i];
        if (t < 128) {
            const int e = e0 + t;
            const int r = g_row[e];
            const int c = g_col[e];
            row_s[t] = r;
            col_s[t] = c;
            const float dx = x[r * 3 + 0] - x[c * 3 + 0];
            const float dy = x[r * 3 + 1] - x[c * 3 + 1];
            const float dz = x[r * 3 + 2] - x[c * 3 + 2];
            rad_s[t] = dx * dx + dy * dy + dz * dz;
        }
        __syncthreads();

        // ---- Phase A: t1 = hA[row] + hB[col] + radial*W1r + ea@W1e ; u = silu(t1)
        {
            const int warp  = t >> 5;
            const int lane  = t & 31;
            const int ebase = warp * 8;
            const int co    = lane * 4;
            float4 a4 = *reinterpret_cast<const float4*>(g_hAB + (size_t)row_s[ebase] * 256 + co);
            float4 b4 = *reinterpret_cast<const float4*>(g_hAB + (size_t)col_s[ebase] * 256 + 128 + co);
#pragma unroll
            for (int ii = 0; ii < 8; ii++) {
                float4 na, nb;
                if (ii < 7) {
                    na = *reinterpret_cast<const float4*>(g_hAB + (size_t)row_s[ebase + ii + 1] * 256 + co);
                    nb = *reinterpret_cast<const float4*>(g_hAB + (size_t)col_s[ebase + ii + 1] * 256 + 128 + co);
                }
                const int e = ebase + ii;
                const float rad = rad_s[e];
                const float4 wr = *reinterpret_cast<const float4*>(W1r_s + co);
                float tx = fmaf(rad, wr.x, a4.x + b4.x);
                float ty = fmaf(rad, wr.y, a4.y + b4.y);
                float tz = fmaf(rad, wr.z, a4.z + b4.z);
                float tw = fmaf(rad, wr.w, a4.w + b4.w);
#pragma unroll
                for (int j = 0; j < 16; j++) {
                    const float ej = ea_s[e * 16 + j];
                    const float4 w = *reinterpret_cast<const float4*>(W1e_s + j * 128 + co);
                    tx = fmaf(ej, w.x, tx);
                    ty = fmaf(ej, w.y, ty);
                    tz = fmaf(ej, w.z, tz);
                    tw = fmaf(ej, w.w, tw);
                }
                *reinterpret_cast<float4*>(u_s + e * 132 + co) =
                    make_float4(silu_f(tx), silu_f(ty), silu_f(tz), silu_f(tw));
                if (ii < 7) { a4 = na; b4 = nb; }
            }
        }
        __syncthreads();

        // ---- Phase B: v = silu(u @ W2 + be2); red.v4 scatter to g_agg[row]
        // Thread map: lane -> 4 contiguous cols (conflict-free LDS.128 on W2),
        //             warp -> 8 edges (u reads are warp-uniform broadcasts).
        {
            const int lane = t & 31;
            const int warp = t >> 5;
            const float* wb = W2_s + lane * 4;
            const float* ub = u_s + (size_t)warp * 8 * 132;

            float acc[8][4];
#pragma unroll
            for (int i = 0; i < 8; i++)
#pragma unroll
                for (int j = 0; j < 4; j++) acc[i][j] = 0.f;

#pragma unroll 4
            for (int k = 0; k < 128; k++) {
                const float4 w = *reinterpret_cast<const float4*>(wb + k * 128);
                float av[8];
#pragma unroll
                for (int i = 0; i < 8; i++) av[i] = ub[i * 132 + k];
#pragma unroll
                for (int i = 0; i < 8; i++) {
                    acc[i][0] = fmaf(av[i], w.x, acc[i][0]);
                    acc[i][1] = fmaf(av[i], w.y, acc[i][1]);
                    acc[i][2] = fmaf(av[i], w.z, acc[i][2]);
                    acc[i][3] = fmaf(av[i], w.w, acc[i][3]);
                }
            }
            const float4 bias = *reinterpret_cast<const float4*>(be2_s + lane * 4);
#pragma unroll
            for (int i = 0; i < 8; i++) {
                const int e = warp * 8 + i;
                float* dst = g_agg + (size_t)row_s[e] * 128 + lane * 4;
                const float v0 = silu_f(acc[i][0] + bias.x);
                const float v1 = silu_f(acc[i][1] + bias.y);
                const float v2 = silu_f(acc[i][2] + bias.z);
                const float v3 = silu_f(acc[i][3] + bias.w);
                asm volatile("red.global.add.v4.f32 [%0], {%1, %2, %3, %4};"
                             :: "l"(dst), "f"(v0), "f"(v1), "f"(v2), "f"(v3) : "memory");
            }
        }
    }
}

// ---------------- node MLP + residual + pooled scatter ----------------
#define NODE_SMEM_FLOATS (256 * 36 + 128 * 33 + 32)
#define NODE_SMEM_BYTES  (NODE_SMEM_FLOATS * 4)

__global__ __launch_bounds__(256) void k_node(const float* __restrict__ h,
                                              const float* __restrict__ Wn1,
                                              const float* __restrict__ bn1,
                                              const float* __restrict__ Wn2,
                                              const float* __restrict__ bn2) {
    extern __shared__ float sm[];
    float* a_s = sm;                      // 256 x 36 (k-major [h|agg])
    float* m_s = sm + 256 * 36;           // 128 x 33 (mid, k-major)
    int*   b_s = reinterpret_cast<int*>(sm + 256 * 36 + 128 * 33);

    const int n0 = blockIdx.x * NTILE;
    const int t = threadIdx.x;
    {
        const int n  = t >> 3;
        const int k4 = t & 7;
        const int ng = n0 + n;
#pragma unroll
        for (int j = 0; j < 4; j++) {
            const int k = k4 * 16 + j * 4;
            float4 v = make_float4(0.f, 0.f, 0.f, 0.f);
            float4 w = make_float4(0.f, 0.f, 0.f, 0.f);
            if (ng < N_NODES) {
                v = *reinterpret_cast<const float4*>(h + (size_t)ng * 128 + k);
                w = *reinterpret_cast<const float4*>(g_agg + (size_t)ng * 128 + k);
            }
            a_s[(k + 0) * 36 + n] = v.x;
            a_s[(k + 1) * 36 + n] = v.y;
            a_s[(k + 2) * 36 + n] = v.z;
            a_s[(k + 3) * 36 + n] = v.w;
            a_s[(128 + k + 0) * 36 + n] = w.x;
            a_s[(128 + k + 1) * 36 + n] = w.y;
            a_s[(128 + k + 2) * 36 + n] = w.z;
            a_s[(128 + k + 3) * 36 + n] = w.w;
        }
        if (t < 32) b_s[t] = (n0 + t < N_NODES) ? g_batch[n0 + t] : 0;
    }
    __syncthreads();

    const int cg = t & 31;  // 32 groups x 4 cols
    const int ng = t >> 5;  // 8 groups x 4 nodes
    float acc[4][4];
#pragma unroll
    for (int i = 0; i < 4; i++)
#pragma unroll
        for (int j = 0; j < 4; j++) acc[i][j] = 0.f;

    for (int k = 0; k < 256; k++) {
        float av[4];
#pragma unroll
        for (int i = 0; i < 4; i++) av[i] = a_s[k * 36 + ng * 4 + i];
        const float4 w = __ldg(reinterpret_cast<const float4*>(Wn1 + k * 128 + cg * 4));
        const float wv[4] = {w.x, w.y, w.z, w.w};
#pragma unroll
        for (int i = 0; i < 4; i++)
#pragma unroll
            for (int j = 0; j < 4; j++) acc[i][j] = fmaf(av[i], wv[j], acc[i][j]);
    }
#pragma unroll
    for (int j = 0; j < 4; j++) {
        const int c = cg * 4 + j;
        const float b = __ldg(bn1 + c);
#pragma unroll
        for (int i = 0; i < 4; i++)
            m_s[c * 33 + ng * 4 + i] = silu_f(acc[i][j] + b);
    }
    __syncthreads();

    float acc2[4][4];
#pragma unroll
    for (int i = 0; i < 4; i++)
#pragma unroll
        for (int j = 0; j < 4; j++) acc2[i][j] = 0.f;

    for (int k = 0; k < 128; k++) {
        float av[4];
#pragma unroll
        for (int i = 0; i < 4; i++) av[i] = m_s[k * 33 + ng * 4 + i];
        const float4 w = __ldg(reinterpret_cast<const float4*>(Wn2 + k * 128 + cg * 4));
        const float wv[4] = {w.x, w.y, w.z, w.w};
#pragma unroll
        for (int i = 0; i < 4; i++)
#pragma unroll
            for (int j = 0; j < 4; j++) acc2[i][j] = fmaf(av[i], wv[j], acc2[i][j]);
    }
#pragma unroll
    for (int i = 0; i < 4; i++) {
        const int n = n0 + ng * 4 + i;
        if (n < N_NODES) {
            const int b = b_s[ng * 4 + i];
#pragma unroll
            for (int j = 0; j < 4; j++) {
                const int c = cg * 4 + j;
                const float hn = acc2[i][j] + __ldg(bn2 + c) + a_s[c * 36 + ng * 4 + i];
                atomicAdd(&g_pool[b * 128 + c], hn);
            }
        }
    }
    if (t < 32 && n0 + t < N_NODES) atomicAdd(&g_cnt[b_s[t]], 1.0f);
}

__global__ void k_pool_final(float* __restrict__ out) {
    const int g = blockIdx.x;
    const int c = threadIdx.x;
    const float cnt = fmaxf(g_cnt[g], 1.0f);
    out[g * 128 + c] = g_pool[g * 128 + c] / cnt;
}

// ---------------- launcher ----------------
extern "C" void kernel_launch(void* const* d_in, const int* in_sizes, int n_in,
                              void* d_out, int out_size) {
    const float* h   = (const float*)d_in[0];
    const void*  ei  = d_in[1];
    const float* x   = (const float*)d_in[2];
    const float* ea  = (const float*)d_in[3];
    const void*  bat = d_in[4];
    const float* We1 = (const float*)d_in[5];
    const float* be1 = (const float*)d_in[6];
    const float* We2 = (const float*)d_in[7];
    const float* be2 = (const float*)d_in[8];
    const float* Wn1 = (const float*)d_in[9];
    const float* bn1 = (const float*)d_in[10];
    const float* Wn2 = (const float*)d_in[11];
    const float* bn2 = (const float*)d_in[12];
    float* out = (float*)d_out;

    cudaFuncSetAttribute(k_edge, cudaFuncAttributeMaxDynamicSharedMemorySize, EDGE_SMEM_BYTES);
    cudaFuncSetAttribute(k_node, cudaFuncAttributeMaxDynamicSharedMemorySize, NODE_SMEM_BYTES);

    k_detect<<<1, 1>>>(ei);
    k_cvt_idx<<<(N_EDGES + 255) / 256, 256>>>(ei, bat);
    k_zero_agg<<<(N_NODES * HID / 4 + 255) / 256, 256>>>();
    k_zero_pool<<<(N_GRAPHS * HID + 255) / 256, 256>>>();
    k_prep_wcat<<<(128 * 256 + 255) / 256, 256>>>(We1);
    k_node_pre<<<(N_NODES + NTILE - 1) / NTILE, 256>>>(h, be1);
    k_edge<<<152, 512, EDGE_SMEM_BYTES>>>(x, ea, We1, We2, be2);
    k_node<<<(N_NODES + NTILE - 1) / NTILE, 256, NODE_SMEM_BYTES>>>(h, Wn1, bn1, Wn2, bn2);
    k_pool_final<<<N_GRAPHS, HID>>>(out);
}

// round 5
// speedup vs baseline: 2.0014x; 1.1365x over previous
#include <cuda_runtime.h>
#include <cuda_bf16.h>
#include <cstdint>

#define N_NODES  50000
#define N_EDGES  800000
#define HID      128
#define EDGE_D   16
#define N_GRAPHS 64

#define ETILE 128
#define NTILE 32
#define NUM_ETILES (N_EDGES / ETILE)

// ---------------- device scratch (static, no allocation) ----------------
__device__ float g_hAB[(size_t)N_NODES * 256];   // hA | hB  (51.2 MB)
__device__ float g_agg[(size_t)N_NODES * HID];   // scatter target (25.6 MB)
__device__ float g_Wcat[128 * 256];              // [We1a | We1b] rearranged
__device__ float g_pool[N_GRAPHS * HID];
__device__ float g_cnt[N_GRAPHS];
__device__ int   g_row[N_EDGES];
__device__ int   g_col[N_EDGES];
__device__ int   g_batch[N_NODES];
__device__ int   g_is64;

__device__ __forceinline__ float silu_f(float v) {
    return __fdividef(v, 1.0f + __expf(-v));
}

// bf16 mma m16n8k16: D += A(16x16) * B(16x8), A row-major, B col-major
__device__ __forceinline__ void mma_bf16(float* d, uint32_t a0, uint32_t a1,
                                         uint32_t a2, uint32_t a3,
                                         uint32_t b0, uint32_t b1) {
    asm volatile(
        "mma.sync.aligned.m16n8k16.row.col.f32.bf16.bf16.f32 "
        "{%0,%1,%2,%3}, {%4,%5,%6,%7}, {%8,%9}, {%0,%1,%2,%3};"
        : "+f"(d[0]), "+f"(d[1]), "+f"(d[2]), "+f"(d[3])
        : "r"(a0), "r"(a1), "r"(a2), "r"(a3), "r"(b0), "r"(b1));
}

// ---------------- small prep kernels ----------------
__global__ void k_detect(const void* __restrict__ ei) {
    const unsigned int* p = (const unsigned int*)ei;
    int is64 = 1;
    for (int i = 0; i < 16; i++) if (p[2 * i + 1] != 0u) is64 = 0;
    g_is64 = is64;
}

__global__ void k_cvt_idx(const void* __restrict__ ei, const void* __restrict__ batch) {
    const int i = blockIdx.x * blockDim.x + threadIdx.x;
    const bool is64 = (g_is64 != 0);
    if (i < N_EDGES) {
        if (is64) {
            const long long* p = (const long long*)ei;
            g_row[i] = (int)p[i];
            g_col[i] = (int)p[N_EDGES + i];
        } else {
            const int* p = (const int*)ei;
            g_row[i] = p[i];
            g_col[i] = p[N_EDGES + i];
        }
    }
    if (i < N_NODES) {
        if (is64) g_batch[i] = (int)((const long long*)batch)[i];
        else      g_batch[i] = ((const int*)batch)[i];
    }
}

__global__ void k_zero_agg() {
    const int i = blockIdx.x * blockDim.x + threadIdx.x;
    if (i < (N_NODES * HID) / 4)
        reinterpret_cast<float4*>(g_agg)[i] = make_float4(0.f, 0.f, 0.f, 0.f);
}

__global__ void k_zero_pool() {
    const int i = blockIdx.x * blockDim.x + threadIdx.x;
    if (i < N_GRAPHS * HID) g_pool[i] = 0.f;
    if (i < N_GRAPHS)       g_cnt[i] = 0.f;
}

__global__ void k_prep_wcat(const float* __restrict__ We1) {
    const int i = blockIdx.x * blockDim.x + threadIdx.x;
    if (i < 128 * 256) {
        const int k = i >> 8, c = i & 255;
        g_Wcat[i] = (c < 128) ? We1[k * 128 + c] : We1[(128 + k) * 128 + (c - 128)];
    }
}

// ---------------- node pre-GEMM: g_hAB[n] = h[n] @ [We1a|We1b] (+be1 on cols<128)
__global__ __launch_bounds__(256) void k_node_pre(const float* __restrict__ h,
                                                  const float* __restrict__ be1) {
    __shared__ float a_s[128 * 36];
    const int n0 = blockIdx.x * NTILE;
    const int t = threadIdx.x;
    {
        const int n  = t >> 3;
        const int k4 = t & 7;
        const int ng = n0 + n;
#pragma unroll
        for (int j = 0; j < 4; j++) {
            const int k = k4 * 16 + j * 4;
            float4 v = make_float4(0.f, 0.f, 0.f, 0.f);
            if (ng < N_NODES) v = *reinterpret_cast<const float4*>(h + (size_t)ng * 128 + k);
            a_s[(k + 0) * 36 + n] = v.x;
            a_s[(k + 1) * 36 + n] = v.y;
            a_s[(k + 2) * 36 + n] = v.z;
            a_s[(k + 3) * 36 + n] = v.w;
        }
    }
    __syncthreads();
    const int cg = t & 31;
    const int ng = t >> 5;
    float acc[4][8];
#pragma unroll
    for (int i = 0; i < 4; i++)
#pragma unroll
        for (int j = 0; j < 8; j++) acc[i][j] = 0.f;

    const float* wbase = g_Wcat + cg * 8;
    for (int k = 0; k < 128; k++) {
        const float4 a  = *reinterpret_cast<const float4*>(&a_s[k * 36 + ng * 4]);
        const float4 w0 = __ldg(reinterpret_cast<const float4*>(wbase + k * 256));
        const float4 w1 = __ldg(reinterpret_cast<const float4*>(wbase + k * 256 + 4));
        const float av[4] = {a.x, a.y, a.z, a.w};
        const float wv[8] = {w0.x, w0.y, w0.z, w0.w, w1.x, w1.y, w1.z, w1.w};
#pragma unroll
        for (int i = 0; i < 4; i++)
#pragma unroll
            for (int j = 0; j < 8; j++) acc[i][j] = fmaf(av[i], wv[j], acc[i][j]);
    }
    const int cbase = cg * 8;
    float bias[8];
#pragma unroll
    for (int j = 0; j < 8; j++) bias[j] = (cbase + j < 128) ? __ldg(be1 + cbase + j) : 0.f;
#pragma unroll
    for (int i = 0; i < 4; i++) {
        const int n = n0 + ng * 4 + i;
        if (n < N_NODES) {
            float4 o0 = make_float4(acc[i][0] + bias[0], acc[i][1] + bias[1],
                                    acc[i][2] + bias[2], acc[i][3] + bias[3]);
            float4 o1 = make_float4(acc[i][4] + bias[4], acc[i][5] + bias[5],
                                    acc[i][6] + bias[6], acc[i][7] + bias[7]);
            *reinterpret_cast<float4*>(g_hAB + (size_t)n * 256 + cbase)     = o0;
            *reinterpret_cast<float4*>(g_hAB + (size_t)n * 256 + cbase + 4) = o1;
        }
    }
}

// ---------------- fused edge kernel (persistent, bf16 mma.sync 3-term GEMM2) ----------------
// smem layout (byte offsets). bf16 tiles use 136-element (272B) row stride: for
// fragment loads lane address/4 mod 32 = 4g+t -> all 32 banks distinct, conflict-free.
#define SB_W2H   0                 // 128x136 bf16 = 34816 B  (W2^T hi, [c][k])
#define SB_W2L   34816             // 34816 B                 (W2^T lo)
#define SB_UHI   69632             // 34816 B                 (u hi, [e][k])
#define SB_ULO   104448            // 34816 B                 (u lo)
#define SB_W1E   139264            // 2048 f32 = 8192 B
#define SB_W1R   147456            // 128 f32
#define SB_BE2   147968            // 128 f32
#define SB_RAD   148480            // 128 f32
#define SB_ROW   148992            // 128 int
#define SB_COL   149504            // 128 int
#define SB_EA    150016            // 2048 f32 = 8192 B
#define EDGE_SMEM_BYTES 158208

#define BSTRIDE 136   // bf16 elements per row

__global__ __launch_bounds__(512, 1) void k_edge(const float* __restrict__ x,
                                                 const float* __restrict__ ea,
                                                 const float* __restrict__ We1,
                                                 const float* __restrict__ We2,
                                                 const float* __restrict__ be2) {
    extern __shared__ char smem[];
    __nv_bfloat16* w2h = reinterpret_cast<__nv_bfloat16*>(smem + SB_W2H);
    __nv_bfloat16* w2l = reinterpret_cast<__nv_bfloat16*>(smem + SB_W2L);
    __nv_bfloat16* uhi = reinterpret_cast<__nv_bfloat16*>(smem + SB_UHI);
    __nv_bfloat16* ulo = reinterpret_cast<__nv_bfloat16*>(smem + SB_ULO);
    float* W1e_s = reinterpret_cast<float*>(smem + SB_W1E);
    float* W1r_s = reinterpret_cast<float*>(smem + SB_W1R);
    float* be2_s = reinterpret_cast<float*>(smem + SB_BE2);
    float* rad_s = reinterpret_cast<float*>(smem + SB_RAD);
    int*   row_s = reinterpret_cast<int*>(smem + SB_ROW);
    int*   col_s = reinterpret_cast<int*>(smem + SB_COL);
    float* ea_s  = reinterpret_cast<float*>(smem + SB_EA);

    const int t = threadIdx.x;
    const int w = t >> 5, lane = t & 31;

    // stage W2^T hi/lo (once per persistent block): We2 is [k][c] -> w2*[c][k]
    for (int i = t; i < 16384; i += 512) {
        const int k = i >> 7, c = i & 127;
        const float v = We2[i];
        const __nv_bfloat16 hi = __float2bfloat16(v);
        w2h[c * BSTRIDE + k] = hi;
        w2l[c * BSTRIDE + k] = __float2bfloat16(v - __bfloat162float(hi));
    }
    for (int i = t; i < 2048; i += 512) W1e_s[i] = We1[257 * 128 + i];
    if (t < 128) {
        W1r_s[t] = We1[256 * 128 + t];
        be2_s[t] = be2[t];
    }

    // Phase-B warp tiling: warp -> m16 (edges) x n64 (cols)
    const int mt = w & 7;        // 8 m-tiles of 16 edges
    const int nh = w >> 3;       // 2 n-halves of 64 cols
    const int g  = lane >> 2;    // 0..7
    const int tq = lane & 3;     // 0..3

    for (int tile = blockIdx.x; tile < NUM_ETILES; tile += gridDim.x) {
        const int e0 = tile * ETILE;
        __syncthreads();   // guard smem tile buffers vs previous iteration readers

        for (int i = t; i < 2048; i += 512) ea_s[i] = ea[(size_t)e0 * 16 + i];
        if (t < 128) {
            const int eg = e0 + t;
            const int r = g_row[eg];
            const int c = g_col[eg];
            row_s[t] = r;
            col_s[t] = c;
            const float dx = x[r * 3 + 0] - x[c * 3 + 0];
            const float dy = x[r * 3 + 1] - x[c * 3 + 1];
            const float dz = x[r * 3 + 2] - x[c * 3 + 2];
            rad_s[t] = dx * dx + dy * dy + dz * dz;
        }
        __syncthreads();

        // ---- Phase A: u = silu(hA[row]+hB[col]+rad*W1r+ea@W1e); split hi/lo bf16 -> smem
        {
            const int ebase = w * 8;
            const int co    = lane * 4;
            float4 a4 = *reinterpret_cast<const float4*>(g_hAB + (size_t)row_s[ebase] * 256 + co);
            float4 b4 = *reinterpret_cast<const float4*>(g_hAB + (size_t)col_s[ebase] * 256 + 128 + co);
#pragma unroll
            for (int ii = 0; ii < 8; ii++) {
                float4 na, nb;
                if (ii < 7) {
                    na = *reinterpret_cast<const float4*>(g_hAB + (size_t)row_s[ebase + ii + 1] * 256 + co);
                    nb = *reinterpret_cast<const float4*>(g_hAB + (size_t)col_s[ebase + ii + 1] * 256 + 128 + co);
                }
                const int e = ebase + ii;
                const float rad = rad_s[e];
                const float4 wr = *reinterpret_cast<const float4*>(W1r_s + co);
                float tx = fmaf(rad, wr.x, a4.x + b4.x);
                float ty = fmaf(rad, wr.y, a4.y + b4.y);
                float tz = fmaf(rad, wr.z, a4.z + b4.z);
                float tw = fmaf(rad, wr.w, a4.w + b4.w);
#pragma unroll
                for (int j = 0; j < 16; j++) {
                    const float ej = ea_s[e * 16 + j];
                    const float4 wv = *reinterpret_cast<const float4*>(W1e_s + j * 128 + co);
                    tx = fmaf(ej, wv.x, tx);
                    ty = fmaf(ej, wv.y, ty);
                    tz = fmaf(ej, wv.z, tz);
                    tw = fmaf(ej, wv.w, tw);
                }
                const float sx = silu_f(tx), sy = silu_f(ty);
                const float sz = silu_f(tz), sw = silu_f(tw);
                const __nv_bfloat16 hx = __float2bfloat16(sx);
                const __nv_bfloat16 hy = __float2bfloat16(sy);
                const __nv_bfloat16 hz = __float2bfloat16(sz);
                const __nv_bfloat16 hw = __float2bfloat16(sw);
                __nv_bfloat162 hp0; hp0.x = hx; hp0.y = hy;
                __nv_bfloat162 hp1; hp1.x = hz; hp1.y = hw;
                uint2 hv;
                hv.x = *reinterpret_cast<uint32_t*>(&hp0);
                hv.y = *reinterpret_cast<uint32_t*>(&hp1);
                *reinterpret_cast<uint2*>(uhi + e * BSTRIDE + co) = hv;
                __nv_bfloat162 lp0;
                lp0.x = __float2bfloat16(sx - __bfloat162float(hx));
                lp0.y = __float2bfloat16(sy - __bfloat162float(hy));
                __nv_bfloat162 lp1;
                lp1.x = __float2bfloat16(sz - __bfloat162float(hz));
                lp1.y = __float2bfloat16(sw - __bfloat162float(hw));
                uint2 lv;
                lv.x = *reinterpret_cast<uint32_t*>(&lp0);
                lv.y = *reinterpret_cast<uint32_t*>(&lp1);
                *reinterpret_cast<uint2*>(ulo + e * BSTRIDE + co) = lv;
                if (ii < 7) { a4 = na; b4 = nb; }
            }
        }
        __syncthreads();

        // ---- Phase B: D = u_hi@W_hi + u_lo@W_hi + u_hi@W_lo via bf16 mma.sync
        {
            float d[8][4];
#pragma unroll
            for (int nt = 0; nt < 8; nt++)
#pragma unroll
                for (int j = 0; j < 4; j++) d[nt][j] = 0.f;

#pragma unroll
            for (int term = 0; term < 3; term++) {
                const __nv_bfloat16* A = (term == 1) ? ulo : uhi;
                const __nv_bfloat16* B = (term == 2) ? w2l : w2h;
                const __nv_bfloat16* Ar0 = A + (mt * 16 + g) * BSTRIDE + 2 * tq;
                const __nv_bfloat16* Ar1 = Ar0 + 8 * BSTRIDE;
                const __nv_bfloat16* Bb  = B + (nh * 64 + g) * BSTRIDE + 2 * tq;
#pragma unroll
                for (int ks = 0; ks < 8; ks++) {
                    const int kb = ks * 16;
                    const uint32_t a0 = *reinterpret_cast<const uint32_t*>(Ar0 + kb);
                    const uint32_t a1 = *reinterpret_cast<const uint32_t*>(Ar1 + kb);
                    const uint32_t a2 = *reinterpret_cast<const uint32_t*>(Ar0 + kb + 8);
                    const uint32_t a3 = *reinterpret_cast<const uint32_t*>(Ar1 + kb + 8);
#pragma unroll
                    for (int nt = 0; nt < 8; nt++) {
                        const __nv_bfloat16* Bp = Bb + nt * 8 * BSTRIDE + kb;
                        const uint32_t b0 = *reinterpret_cast<const uint32_t*>(Bp);
                        const uint32_t b1 = *reinterpret_cast<const uint32_t*>(Bp + 8);
                        mma_bf16(d[nt], a0, a1, a2, a3, b0, b1);
                    }
                }
            }

            // epilogue: silu(+bias) then red.v2 scatter (cols come in aligned even pairs)
            const int er0 = row_s[mt * 16 + g];
            const int er1 = row_s[mt * 16 + g + 8];
#pragma unroll
            for (int nt = 0; nt < 8; nt++) {
                const int col = nh * 64 + nt * 8 + 2 * tq;
                const float b0v = be2_s[col];
                const float b1v = be2_s[col + 1];
                const float v00 = silu_f(d[nt][0] + b0v);
                const float v01 = silu_f(d[nt][1] + b1v);
                const float v10 = silu_f(d[nt][2] + b0v);
                const float v11 = silu_f(d[nt][3] + b1v);
                asm volatile("red.global.add.v2.f32 [%0], {%1, %2};"
                             :: "l"(g_agg + (size_t)er0 * 128 + col), "f"(v00), "f"(v01) : "memory");
                asm volatile("red.global.add.v2.f32 [%0], {%1, %2};"
                             :: "l"(g_agg + (size_t)er1 * 128 + col), "f"(v10), "f"(v11) : "memory");
            }
        }
    }
}

// ---------------- node MLP + residual + pooled scatter ----------------
#define NODE_SMEM_FLOATS (256 * 36 + 128 * 33 + 32)
#define NODE_SMEM_BYTES  (NODE_SMEM_FLOATS * 4)

__global__ __launch_bounds__(256) void k_node(const float* __restrict__ h,
                                              const float* __restrict__ Wn1,
                                              const float* __restrict__ bn1,
                                              const float* __restrict__ Wn2,
                                              const float* __restrict__ bn2) {
    extern __shared__ float sm[];
    float* a_s = sm;
    float* m_s = sm + 256 * 36;
    int*   b_s = reinterpret_cast<int*>(sm + 256 * 36 + 128 * 33);

    const int n0 = blockIdx.x * NTILE;
    const int t = threadIdx.x;
    {
        const int n  = t >> 3;
        const int k4 = t & 7;
        const int ng = n0 + n;
#pragma unroll
        for (int j = 0; j < 4; j++) {
            const int k = k4 * 16 + j * 4;
            float4 v = make_float4(0.f, 0.f, 0.f, 0.f);
            float4 w = make_float4(0.f, 0.f, 0.f, 0.f);
            if (ng < N_NODES) {
                v = *reinterpret_cast<const float4*>(h + (size_t)ng * 128 + k);
                w = *reinterpret_cast<const float4*>(g_agg + (size_t)ng * 128 + k);
            }
            a_s[(k + 0) * 36 + n] = v.x;
            a_s[(k + 1) * 36 + n] = v.y;
            a_s[(k + 2) * 36 + n] = v.z;
            a_s[(k + 3) * 36 + n] = v.w;
            a_s[(128 + k + 0) * 36 + n] = w.x;
            a_s[(128 + k + 1) * 36 + n] = w.y;
            a_s[(128 + k + 2) * 36 + n] = w.z;
            a_s[(128 + k + 3) * 36 + n] = w.w;
        }
        if (t < 32) b_s[t] = (n0 + t < N_NODES) ? g_batch[n0 + t] : 0;
    }
    __syncthreads();

    const int cg = t & 31;
    const int ng = t >> 5;
    float acc[4][4];
#pragma unroll
    for (int i = 0; i < 4; i++)
#pragma unroll
        for (int j = 0; j < 4; j++) acc[i][j] = 0.f;

    for (int k = 0; k < 256; k++) {
        float av[4];
#pragma unroll
        for (int i = 0; i < 4; i++) av[i] = a_s[k * 36 + ng * 4 + i];
        const float4 w = __ldg(reinterpret_cast<const float4*>(Wn1 + k * 128 + cg * 4));
        const float wv[4] = {w.x, w.y, w.z, w.w};
#pragma unroll
        for (int i = 0; i < 4; i++)
#pragma unroll
            for (int j = 0; j < 4; j++) acc[i][j] = fmaf(av[i], wv[j], acc[i][j]);
    }
#pragma unroll
    for (int j = 0; j < 4; j++) {
        const int c = cg * 4 + j;
        const float b = __ldg(bn1 + c);
#pragma unroll
        for (int i = 0; i < 4; i++)
            m_s[c * 33 + ng * 4 + i] = silu_f(acc[i][j] + b);
    }
    __syncthreads();

    float acc2[4][4];
#pragma unroll
    for (int i = 0; i < 4; i++)
#pragma unroll
        for (int j = 0; j < 4; j++) acc2[i][j] = 0.f;

    for (int k = 0; k < 128; k++) {
        float av[4];
#pragma unroll
        for (int i = 0; i < 4; i++) av[i] = m_s[k * 33 + ng * 4 + i];
        const float4 w = __ldg(reinterpret_cast<const float4*>(Wn2 + k * 128 + cg * 4));
        const float wv[4] = {w.x, w.y, w.z, w.w};
#pragma unroll
        for (int i = 0; i < 4; i++)
#pragma unroll
            for (int j = 0; j < 4; j++) acc2[i][j] = fmaf(av[i], wv[j], acc2[i][j]);
    }
#pragma unroll
    for (int i = 0; i < 4; i++) {
        const int n = n0 + ng * 4 + i;
        if (n < N_NODES) {
            const int b = b_s[ng * 4 + i];
#pragma unroll
            for (int j = 0; j < 4; j++) {
                const int c = cg * 4 + j;
                const float hn = acc2[i][j] + __ldg(bn2 + c) + a_s[c * 36 + ng * 4 + i];
                atomicAdd(&g_pool[b * 128 + c], hn);
            }
        }
    }
    if (t < 32 && n0 + t < N_NODES) atomicAdd(&g_cnt[b_s[t]], 1.0f);
}

__global__ void k_pool_final(float* __restrict__ out) {
    const int g = blockIdx.x;
    const int c = threadIdx.x;
    const float cnt = fmaxf(g_cnt[g], 1.0f);
    out[g * 128 + c] = g_pool[g * 128 + c] / cnt;
}

// ---------------- launcher ----------------
extern "C" void kernel_launch(void* const* d_in, const int* in_sizes, int n_in,
                              void* d_out, int out_size) {
    const float* h   = (const float*)d_in[0];
    const void*  ei  = d_in[1];
    const float* x   = (const float*)d_in[2];
    const float* ea  = (const float*)d_in[3];
    const void*  bat = d_in[4];
    const float* We1 = (const float*)d_in[5];
    const float* be1 = (const float*)d_in[6];
    const float* We2 = (const float*)d_in[7];
    const float* be2 = (const float*)d_in[8];
    const float* Wn1 = (const float*)d_in[9];
    const float* bn1 = (const float*)d_in[10];
    const float* Wn2 = (const float*)d_in[11];
    const float* bn2 = (const float*)d_in[12];
    float* out = (float*)d_out;

    cudaFuncSetAttribute(k_edge, cudaFuncAttributeMaxDynamicSharedMemorySize, EDGE_SMEM_BYTES);
    cudaFuncSetAttribute(k_node, cudaFuncAttributeMaxDynamicSharedMemorySize, NODE_SMEM_BYTES);

    k_detect<<<1, 1>>>(ei);
    k_cvt_idx<<<(N_EDGES + 255) / 256, 256>>>(ei, bat);
    k_zero_agg<<<(N_NODES * HID / 4 + 255) / 256, 256>>>();
    k_zero_pool<<<(N_GRAPHS * HID + 255) / 256, 256>>>();
    k_prep_wcat<<<(128 * 256 + 255) / 256, 256>>>(We1);
    k_node_pre<<<(N_NODES + NTILE - 1) / NTILE, 256>>>(h, be1);
    k_edge<<<152, 512, EDGE_SMEM_BYTES>>>(x, ea, We1, We2, be2);
    k_node<<<(N_NODES + NTILE - 1) / NTILE, 256, NODE_SMEM_BYTES>>>(h, Wn1, bn1, Wn2, bn2);
    k_pool_final<<<N_GRAPHS, HID>>>(out);
}